// round 2
// baseline (speedup 1.0000x reference)
#include <cuda_runtime.h>

#define N_MAX 100000
#define D 64

// Scratch (allocation-free rule: __device__ globals)
__device__ float g_deg[N_MAX];
__device__ float g_dinv[N_MAX];
__device__ float g_xl[N_MAX];
__device__ float g_xr[N_MAX];
__device__ float g_h1[(size_t)N_MAX * D];
__device__ float g_acc[(size_t)N_MAX * D];

// ---------------------------------------------------------------------------
__global__ void k_zero_deg(int n) {
    int i = blockIdx.x * blockDim.x + threadIdx.x;
    if (i < n) g_deg[i] = 0.f;
}

__global__ void k_deg(const int* __restrict__ dst, int E) {
    int i = blockIdx.x * blockDim.x + threadIdx.x;
    int stride = gridDim.x * blockDim.x;
    for (; i < E; i += stride)
        atomicAdd(&g_deg[dst[i]], 1.0f);
}

// Per-node (1 warp/node): dinv, dots x.att_l / x.att_r, zero acc row.
__global__ void k_prep(const float* __restrict__ x,
                       const float* __restrict__ att_l,
                       const float* __restrict__ att_r, int n) {
    int warp = (blockIdx.x * blockDim.x + threadIdx.x) >> 5;
    int lane = threadIdx.x & 31;
    if (warp >= n) return;
    float2 v  = ((const float2*)(x + (size_t)warp * D))[lane];
    float2 al = ((const float2*)att_l)[lane];
    float2 ar = ((const float2*)att_r)[lane];
    float dl = v.x * al.x + v.y * al.y;
    float dr = v.x * ar.x + v.y * ar.y;
    #pragma unroll
    for (int o = 16; o; o >>= 1) {
        dl += __shfl_down_sync(0xffffffffu, dl, o);
        dr += __shfl_down_sync(0xffffffffu, dr, o);
    }
    ((float2*)(g_acc + (size_t)warp * D))[lane] = make_float2(0.f, 0.f);
    if (lane == 0) {
        g_xl[warp] = dl;
        g_xr[warp] = dr;
        float d = g_deg[warp];
        g_dinv[warp] = (d > 0.f) ? rsqrtf(d) : 0.f;
    }
}

// Edge scatter: warp handles 2 edges, 16 lanes each, float4 payload + red.v4.
__global__ void k_scatter(const float* __restrict__ feat,
                          const int* __restrict__ src,
                          const int* __restrict__ dst, int E) {
    int gw   = (blockIdx.x * blockDim.x + threadIdx.x) >> 5;
    int lane = threadIdx.x & 31;
    int half = lane >> 4;   // which edge of the pair
    int li   = lane & 15;   // float4 index within the row
    int nw   = (gridDim.x * blockDim.x) >> 5;
    for (int base = gw * 2; base < E; base += nw * 2) {
        int e = base + half;
        if (e < E) {
            int s = src[e];
            int t = dst[e];
            float w = tanhf(g_xl[s] + g_xr[t]) * g_dinv[s] * g_dinv[t];
            if (w != 0.f) {
                float4 v = ((const float4*)(feat + (size_t)s * D))[li];
                float* p = g_acc + (size_t)t * D + li * 4;
                asm volatile(
                    "red.global.add.v4.f32 [%0], {%1,%2,%3,%4};"
                    :: "l"(p), "f"(v.x * w), "f"(v.y * w),
                       "f"(v.z * w), "f"(v.w * w)
                    : "memory");
            }
        }
    }
}

// Per-node: h1 = acc + 0.5*x (store), dots of h1 with att, re-zero acc.
__global__ void k_mid(const float* __restrict__ x,
                      const float* __restrict__ att_l,
                      const float* __restrict__ att_r, int n) {
    int warp = (blockIdx.x * blockDim.x + threadIdx.x) >> 5;
    int lane = threadIdx.x & 31;
    if (warp >= n) return;
    float2* accp = (float2*)(g_acc + (size_t)warp * D);
    float2 a  = accp[lane];
    float2 xv = ((const float2*)(x + (size_t)warp * D))[lane];
    float2 h  = make_float2(a.x + 0.5f * xv.x, a.y + 0.5f * xv.y);
    ((float2*)(g_h1 + (size_t)warp * D))[lane] = h;
    float2 al = ((const float2*)att_l)[lane];
    float2 ar = ((const float2*)att_r)[lane];
    float dl = h.x * al.x + h.y * al.y;
    float dr = h.x * ar.x + h.y * ar.y;
    #pragma unroll
    for (int o = 16; o; o >>= 1) {
        dl += __shfl_down_sync(0xffffffffu, dl, o);
        dr += __shfl_down_sync(0xffffffffu, dr, o);
    }
    accp[lane] = make_float2(0.f, 0.f);
    if (lane == 0) {
        g_xl[warp] = dl;
        g_xr[warp] = dr;
    }
}

// Per-node epilogue: h2 = acc + 0.5*x; out = h2 @ pred_w^T + pred_b.
__global__ void k_final(const float* __restrict__ x,
                        const float* __restrict__ pw,
                        const float* __restrict__ pb,
                        float* __restrict__ out, int n) {
    int warp = (blockIdx.x * blockDim.x + threadIdx.x) >> 5;
    int lane = threadIdx.x & 31;
    if (warp >= n) return;
    float2 a  = ((const float2*)(g_acc + (size_t)warp * D))[lane];
    float2 xv = ((const float2*)(x + (size_t)warp * D))[lane];
    float2 h  = make_float2(a.x + 0.5f * xv.x, a.y + 0.5f * xv.y);
    float2 w0 = ((const float2*)pw)[lane];        // pred_w row 0
    float2 w1 = ((const float2*)(pw + D))[lane];  // pred_w row 1
    float d0 = h.x * w0.x + h.y * w0.y;
    float d1 = h.x * w1.x + h.y * w1.y;
    #pragma unroll
    for (int o = 16; o; o >>= 1) {
        d0 += __shfl_down_sync(0xffffffffu, d0, o);
        d1 += __shfl_down_sync(0xffffffffu, d1, o);
    }
    if (lane == 0) {
        out[(size_t)warp * 2 + 0] = d0 + pb[0];
        out[(size_t)warp * 2 + 1] = d1 + pb[1];
    }
}

// ---------------------------------------------------------------------------
extern "C" void kernel_launch(void* const* d_in, const int* in_sizes, int n_in,
                              void* d_out, int out_size) {
    const float* x     = (const float*)d_in[0];
    const int*   edges = (const int*)d_in[1];
    const float* att_l = (const float*)d_in[2];
    const float* att_r = (const float*)d_in[3];
    const float* pw    = (const float*)d_in[4];
    const float* pb    = (const float*)d_in[5];
    float* out = (float*)d_out;

    int N = in_sizes[0] / D;
    int E = in_sizes[1] / 2;
    const int* src = edges;
    const int* dst = edges + E;

    int node_blocks = (N * 32 + 255) / 256;   // 1 warp per node
    int deg_blocks  = (E + 255) / 256;
    int scat_blocks = 4096;                   // grid-stride, 2 edges/warp

    float* h1;
    cudaGetSymbolAddress((void**)&h1, g_h1);

    k_zero_deg<<<(N + 255) / 256, 256>>>(N);
    k_deg<<<deg_blocks, 256>>>(dst, E);
    k_prep<<<node_blocks, 256>>>(x, att_l, att_r, N);
    k_scatter<<<scat_blocks, 256>>>(x, src, dst, E);
    k_mid<<<node_blocks, 256>>>(x, att_l, att_r, N);
    k_scatter<<<scat_blocks, 256>>>(h1, src, dst, E);
    k_final<<<node_blocks, 256>>>(x, pw, pb, out, N);
}